// round 15
// baseline (speedup 1.0000x reference)
#include <cuda_runtime.h>
#include <cuda_bf16.h>

// Fused gather with 256-bit (v8.f32) global accesses (sm_100+ LDG.E.256/STG.E.256).
//   block = (32, 8) = 256 threads; one warp = one full 1024B output row.
//   ITEMS = 2 slots per thread -> 16 slots per block; grid = (maxlen/16, B).
// Warp 0 computes starts[bid] (reduce over the 1KB L1-hot length array) and
// broadcasts via shared. All offsets 32-bit.
// R13 change: stores use default write-back policy (no .cs) so L2 can
// aggregate dirty lines and drain opportunistically; loads stay streaming.
#define CDBA_WARPS  8
#define CDBA_ITEMS  2

__device__ __forceinline__ void ldg256_cs(const float* p, float* v) {
    asm volatile("ld.global.cs.v8.f32 {%0,%1,%2,%3,%4,%5,%6,%7}, [%8];"
        : "=f"(v[0]), "=f"(v[1]), "=f"(v[2]), "=f"(v[3]),
          "=f"(v[4]), "=f"(v[5]), "=f"(v[6]), "=f"(v[7])
        : "l"(p));
}

__device__ __forceinline__ void stg256_wb(float* p, const float* v) {
    asm volatile("st.global.v8.f32 [%0], {%1,%2,%3,%4,%5,%6,%7,%8};"
        :: "l"(p),
           "f"(v[0]), "f"(v[1]), "f"(v[2]), "f"(v[3]),
           "f"(v[4]), "f"(v[5]), "f"(v[6]), "f"(v[7])
        : "memory");
}

__global__ void __launch_bounds__(256)
cdba_fused_kernel(const float* __restrict__ attr,
                  const int*   __restrict__ len,
                  float*       __restrict__ out,
                  int rowF8,      // F/8 (32)
                  int maxlen)     // MAX_LEN (1024)
{
    __shared__ int s_start, s_len;

    const int col = threadIdx.x;                         // 0..31 (float8 column)
    const int bid = blockIdx.y;                          // graph id
    const int tid = threadIdx.x + threadIdx.y * blockDim.x;

    if (tid < 32) {
        // Exclusive prefix: start = sum_{j<bid} len[j]; one warp only.
        int s = 0;
        for (int j = tid; j < bid; j += 32)
            s += __ldg(&len[j]);
        #pragma unroll
        for (int off = 16; off > 0; off >>= 1)
            s += __shfl_xor_sync(0xffffffffu, s, off);
        if (tid == 0) {
            s_start = s;
            s_len   = __ldg(&len[bid]);
        }
    }
    __syncthreads();
    const int start = s_start;
    const int L     = s_len;

    const int slot0 = blockIdx.x * (CDBA_WARPS * CDBA_ITEMS) + threadIdx.y;

    // 32-bit float8-granule offsets: max = B*MAX_LEN*rowF8 = 8.4M < 2^31.
    const unsigned outBase = ((unsigned)bid * (unsigned)maxlen) * (unsigned)rowF8
                             + (unsigned)col;
    const unsigned srcBase = (unsigned)start * (unsigned)rowF8 + (unsigned)col;

    float v[CDBA_ITEMS][8];
    #pragma unroll
    for (int k = 0; k < CDBA_ITEMS; k++) {
        int slot = slot0 + k * CDBA_WARPS;
        if (slot < L) {
            ldg256_cs(attr + 8u * (srcBase + (unsigned)slot * (unsigned)rowF8), v[k]);
        } else {
            #pragma unroll
            for (int j = 0; j < 8; j++) v[k][j] = 0.f;
        }
    }
    #pragma unroll
    for (int k = 0; k < CDBA_ITEMS; k++) {
        int slot = slot0 + k * CDBA_WARPS;
        stg256_wb(out + 8u * (outBase + (unsigned)slot * (unsigned)rowF8), v[k]);
    }
}

extern "C" void kernel_launch(void* const* d_in, const int* in_sizes, int n_in,
                              void* d_out, int out_size) {
    // metadata order: attr (f32, N*F), graph_id_attr (i32, N), attr_len (i32, B)
    const float* attr = (const float*)d_in[0];
    const int*   alen = (const int*)  d_in[2];

    int n_nodes  = in_sizes[1];                 // N
    int b        = in_sizes[2];                 // B
    int f        = in_sizes[0] / n_nodes;       // F (256)
    int rowF8    = f / 8;                       // 32
    int maxlen   = out_size / (b * f);          // 1024

    dim3 block(32, CDBA_WARPS);                                        // 256 threads
    int slotsPerBlock = CDBA_WARPS * CDBA_ITEMS;                       // 16
    dim3 grid((maxlen + slotsPerBlock - 1) / slotsPerBlock, b);        // (64, 256)
    cdba_fused_kernel<<<grid, block>>>(
        attr, alen, (float*)d_out, rowF8, maxlen);
}